// round 5
// baseline (speedup 1.0000x reference)
#include <cuda_runtime.h>
#include <cuda_bf16.h>

#define N_TFH 1000
#define N_TG  20000
#define N_E   4000000
#define NV    (N_E / 4)
#define N_TAB (N_TG + N_TFH)
#define THREADS 1024
#define BLOCKS  148

__device__ __forceinline__ float warp_reduce(float v) {
    #pragma unroll
    for (int o = 16; o > 0; o >>= 1)
        v += __shfl_xor_sync(0xFFFFFFFFu, v, o);
    return v;
}

__global__ void zero_out_kernel(float* out) { out[0] = 0.0f; }

// Persistent kernel. Each block caches the combined (mu,sigma) table
// (TG entries [0,N_TG), TF_high entries [N_TG,N_TAB)) in shared memory,
// then grid-strides over the 1M float4 edge groups. Gathers hit the smem
// crossbar instead of generating ~32 L1tex wavefronts per warp-gather.
__global__ __launch_bounds__(THREADS, 1)
void fused_loss_kernel(
    const float* __restrict__ TF_high_mu,
    const float* __restrict__ TF_high_sigma,
    const float* __restrict__ TG_mu,
    const float* __restrict__ TG_sigma,
    const float* __restrict__ TF_high_exp,
    const float* __restrict__ TG_exp,
    const float4* __restrict__ k_edge,
    const float4* __restrict__ alpha,
    const float4* __restrict__ cov,
    const float4* __restrict__ edge_y,
    const float4* __restrict__ edge_x,
    const int*   __restrict__ father_num,
    const int4*  __restrict__ idx_tf_tg,
    const int4*  __restrict__ idx_tf_high,
    const int4*  __restrict__ edge_tg_idx,
    const int4*  __restrict__ is_high,
    float* __restrict__ out)
{
    extern __shared__ float2 s_tab[];   // N_TAB float2 = 168 KB

    const float HALF_LOG2PI = 0.918938533204672742f;

    // Build combined table from coalesced reads.
    for (int i = threadIdx.x; i < N_TG; i += THREADS)
        s_tab[i] = make_float2(TG_mu[i], TG_sigma[i]);
    for (int i = threadIdx.x; i < N_TFH; i += THREADS)
        s_tab[N_TG + i] = make_float2(TF_high_mu[i], TF_high_sigma[i]);
    __syncthreads();

    float acc = 0.0f;
    const int gtid   = blockIdx.x * THREADS + threadIdx.x;
    const int stride = gridDim.x * THREADS;

    // p term (N_TFH elems) and q term (N_TG elems) — negligible cost.
    if (gtid < N_TG) {
        float2 t = s_tab[gtid];
        float x = TG_exp[gtid];
        float fn = (float)father_num[gtid];
        float z = (x - t.x) / t.y;
        float lp = -0.5f * z * z - __logf(t.y) - HALF_LOG2PI;
        acc += (fn - 1.0f) * lp;           // contributes -q
    }
    if (gtid < N_TFH) {
        float2 t = s_tab[N_TG + gtid];
        float x = TF_high_exp[gtid];
        float z = (x - t.x) / t.y;
        acc += 0.5f * z * z + __logf(t.y) + HALF_LOG2PI;   // contributes -p
    }

    // Edge term: -kterm accumulated.
    for (int v = gtid; v < NV; v += stride) {
        float4 ke = k_edge[v];
        float4 al = alpha[v];
        float4 cv = cov[v];
        float4 ey = edge_y[v];
        float4 ex = edge_x[v];
        int4  itg = idx_tf_tg[v];
        int4  ith = idx_tf_high[v];
        int4  ieg = edge_tg_idx[v];
        int4  ih  = is_high[v];

        const float* kef = &ke.x;
        const float* alf = &al.x;
        const float* cvf = &cv.x;
        const float* eyf = &ey.x;
        const float* exf = &ex.x;
        const int*  itgf = &itg.x;
        const int*  ithf = &ith.x;
        const int*  iegf = &ieg.x;
        const int*  ihf  = &ih.x;

        #pragma unroll
        for (int l = 0; l < 4; l++) {
            int tfi = ihf[l] ? (N_TG + ithf[l]) : itgf[l];
            float2 tf = s_tab[tfi];          // (tf_mu, tf_sigma)
            float2 tg = s_tab[iegf[l]];      // (tg_mu, tg_sigma)

            float inv_var = __frcp_rn(tf.y * tf.y);
            float loc = tg.x + kef[l] * cvf[l] * (eyf[l] - tf.x) * inv_var;
            loc = fmaxf(loc, 0.0f) + 0.01f;
            float var = tg.y * tg.y - alf[l] * alf[l] * inv_var;
            var = fmaxf(var, 0.0f) + 0.01f;

            float dx = exf[l] - loc;
            // -logprob = 0.5*dx^2/var + 0.5*log(var) + 0.5*log(2pi)
            acc += 0.5f * (dx * dx * __frcp_rn(var) + __logf(var)) + HALF_LOG2PI;
        }
    }

    // Block reduction -> one atomic per block.
    acc = warp_reduce(acc);
    __shared__ float warp_sums[THREADS / 32];
    int lane = threadIdx.x & 31;
    int wid  = threadIdx.x >> 5;
    if (lane == 0) warp_sums[wid] = acc;
    __syncthreads();
    if (wid == 0) {
        float v = (lane < THREADS / 32) ? warp_sums[lane] : 0.0f;
        v = warp_reduce(v);
        if (lane == 0) atomicAdd(out, v);
    }
}

extern "C" void kernel_launch(void* const* d_in, const int* in_sizes, int n_in,
                              void* d_out, int out_size) {
    const float* TF_high_mu    = (const float*)d_in[0];
    const float* TF_high_sigma = (const float*)d_in[1];
    const float* TG_mu         = (const float*)d_in[2];
    const float* TG_sigma      = (const float*)d_in[3];
    const float* TF_high_exp   = (const float*)d_in[4];
    const float* TG_exp        = (const float*)d_in[5];
    const float4* k_edge       = (const float4*)d_in[6];
    const float4* alpha        = (const float4*)d_in[7];
    const float4* cov          = (const float4*)d_in[8];
    const float4* edge_y       = (const float4*)d_in[9];
    const float4* edge_x       = (const float4*)d_in[10];
    const int*  father_num     = (const int*)d_in[11];
    const int4* idx_tf_tg      = (const int4*)d_in[12];
    const int4* idx_tf_high    = (const int4*)d_in[13];
    const int4* edge_tg_idx    = (const int4*)d_in[14];
    const int4* is_high        = (const int4*)d_in[15];
    float* out = (float*)d_out;

    static bool attr_set = false;
    if (!attr_set) {
        cudaFuncSetAttribute(fused_loss_kernel,
                             cudaFuncAttributeMaxDynamicSharedMemorySize,
                             N_TAB * (int)sizeof(float2));
        attr_set = true;
    }

    zero_out_kernel<<<1, 1>>>(out);

    fused_loss_kernel<<<BLOCKS, THREADS, N_TAB * sizeof(float2)>>>(
        TF_high_mu, TF_high_sigma, TG_mu, TG_sigma, TF_high_exp, TG_exp,
        k_edge, alpha, cov, edge_y, edge_x,
        father_num, idx_tf_tg, idx_tf_high, edge_tg_idx, is_high, out);
}